// round 6
// baseline (speedup 1.0000x reference)
#include <cuda_runtime.h>
#include <float.h>

// Problem constants (from reference)
#define B      2
#define C      3
#define T      8
#define H      448
#define W      448
#define NKEY   4
#define L      196      // 14*14
#define GH     14
#define R      121      // 11*11
#define NS     500      // noise samples
#define BK     (B*NKEY) // 8
#define OUTHW  128      // s*A = 4*32

// Per-key compacted weight lists (device scratch — no allocation allowed)
__device__ float g_wc[BK][R];
__device__ int   g_off[BK][R];
__device__ int   g_nnz[BK];

// ---------------------------------------------------------------------------
// Kernel 1: region scores -> min-max norm -> perturbed top-1 histogram ->
// compacted (weight, x-byte-offset) list per key. One block per bk (8 blocks).
// ---------------------------------------------------------------------------
__global__ void weights_kernel(const float* __restrict__ score,
                               const float* __restrict__ noise,
                               const float* __restrict__ sigma_p)
{
    const int bk  = blockIdx.x;
    const int tid = threadIdx.x;

    __shared__ float sc[R];
    __shared__ int   counts[R];
    __shared__ float red[128];
    __shared__ float lo_s, hi_s;

    const float sigma = sigma_p[0];

    // 4x4 window mean over the 14x14 score grid (row-major sum order, /16)
    if (tid < R) {
        const int ri = tid / 11;
        const int rj = tid % 11;
        const float* sp = score + bk * L;
        float s = 0.f;
        #pragma unroll
        for (int ki = 0; ki < 4; ki++)
            #pragma unroll
            for (int kj = 0; kj < 4; kj++)
                s += sp[(ri + ki) * GH + (rj + kj)];
        sc[tid] = s * (1.f / 16.f);
        counts[tid] = 0;
    }
    __syncthreads();

    // min reduction
    red[tid] = (tid < R) ? sc[tid] : FLT_MAX;
    __syncthreads();
    for (int s = 64; s > 0; s >>= 1) {
        if (tid < s) red[tid] = fminf(red[tid], red[tid + s]);
        __syncthreads();
    }
    if (tid == 0) lo_s = red[0];
    __syncthreads();

    // max reduction
    red[tid] = (tid < R) ? sc[tid] : -FLT_MAX;
    __syncthreads();
    for (int s = 64; s > 0; s >>= 1) {
        if (tid < s) red[tid] = fmaxf(red[tid], red[tid + s]);
        __syncthreads();
    }
    if (tid == 0) hi_s = red[0];
    __syncthreads();

    // normalize: (x - lo) / (hi - lo + 1e-5)
    if (tid < R) {
        float inv = 1.f / (hi_s - lo_s + 1e-5f);
        sc[tid] = (sc[tid] - lo_s) * inv;
    }
    __syncthreads();

    // 500 perturbed argmaxes (top-1, first-max-wins like lax.top_k)
    const float* np = noise + (size_t)bk * NS * R;
    for (int n = tid; n < NS; n += 128) {
        const float* nn = np + (size_t)n * R;
        float best = sc[0] + nn[0] * sigma;
        int   bi   = 0;
        for (int r = 1; r < R; r++) {
            float p = sc[r] + nn[r] * sigma;
            if (p > best) { best = p; bi = r; }
        }
        atomicAdd(&counts[bi], 1);
    }
    __syncthreads();

    // deterministic serial compaction: weight + precomputed x offset
    if (tid == 0) {
        int nz = 0;
        for (int r = 0; r < R; r++) {
            int cnt = counts[r];
            if (cnt > 0) {
                int ri = r / 11;
                int rj = r % 11;
                g_wc[bk][nz]  = (float)cnt * (1.f / (float)NS);
                g_off[bk][nz] = ri * 32 * W + rj * 32;   // element offset into x plane
                nz++;
            }
        }
        g_nnz[bk] = nz;
    }
}

// ---------------------------------------------------------------------------
// Kernel 2: fused gather + weighted sum. One block per output row of 128.
//   out[b,c,t,y,x] = sum_i wc[i] * x[b,c,t, y + 32*ri, x + 32*rj]
// blockIdx.x = ((b*3+c)*8 + t)*128 + y, threadIdx.x = x  (coalesced rows)
// ---------------------------------------------------------------------------
__global__ void gather_kernel(const float* __restrict__ x,
                              const int*   __restrict__ group_id,
                              float*       __restrict__ out)
{
    const int row   = blockIdx.x;
    const int tid   = threadIdx.x;
    const int y     = row & (OUTHW - 1);
    const int rowhi = row >> 7;          // (b*3+c)*8 + t
    const int t     = rowhi & 7;
    const int bc    = rowhi >> 3;        // b*3 + c
    const int c     = bc % 3;
    const int b     = bc / 3;

    const int bk  = b * NKEY + group_id[b * T + t];

    __shared__ float wc[R];
    __shared__ int   off[R];

    const int nnz = g_nnz[bk];
    if (tid < nnz) {
        wc[tid]  = g_wc[bk][tid];
        off[tid] = g_off[bk][tid];
    }
    __syncthreads();

    const size_t xbase = (((size_t)(b * 3 + c) * T + t) * H + y) * W + tid;

    float acc = 0.f;
    for (int i = 0; i < nnz; i++)
        acc = fmaf(wc[i], __ldg(&x[xbase + off[i]]), acc);

    out[(size_t)row * OUTHW + tid] = acc;
}

// ---------------------------------------------------------------------------
// Launch: inputs (metadata order): x, score, noise, sigma, group_id
// ---------------------------------------------------------------------------
extern "C" void kernel_launch(void* const* d_in, const int* in_sizes, int n_in,
                              void* d_out, int out_size)
{
    const float* x        = (const float*)d_in[0];
    const float* score    = (const float*)d_in[1];
    const float* noise    = (const float*)d_in[2];
    const float* sigma    = (const float*)d_in[3];
    const int*   group_id = (const int*)  d_in[4];
    float*       out      = (float*)d_out;

    weights_kernel<<<BK, 128>>>(score, noise, sigma);

    const int nrows = B * C * T * OUTHW;   // 6144
    gather_kernel<<<nrows, 128>>>(x, group_id, out);
}

// round 7
// speedup vs baseline: 2.1011x; 2.1011x over previous
#include <cuda_runtime.h>
#include <float.h>

// Problem constants
#define B      2
#define C      3
#define T      8
#define H      448
#define W      448
#define NKEY   4
#define L      196      // 14*14
#define GH     14
#define R      121      // 11*11
#define NS     500
#define BK     (B*NKEY) // 8
#define OUTHW  128      // s*A

// Device scratch (no allocation allowed)
__device__ int   g_arg[BK * NS];     // per-sample argmax region
__device__ float g_wc[BK][R];        // compacted weights
__device__ int   g_off[BK][R];       // compacted x element offsets
__device__ int   g_nnz[BK];

// ---------------------------------------------------------------------------
// Kernel 1: per-(key,sample) perturbed top-1 argmax. One warp per sample.
// grid = (NS/4, BK), block = 128. Each block redundantly computes the
// normalized region scores (cheap), then 4 warps each argmax one sample.
// ---------------------------------------------------------------------------
__global__ void argmax_kernel(const float* __restrict__ score,
                              const float* __restrict__ noise,
                              const float* __restrict__ sigma_p)
{
    const int bk   = blockIdx.y;
    const int tid  = threadIdx.x;
    const int lane = tid & 31;
    const int wrp  = tid >> 5;

    __shared__ float sc[128];
    __shared__ float red[128];
    __shared__ float lo_s, hi_s;

    const float sigma = sigma_p[0];

    // 4x4 window mean over the 14x14 score grid (row-major order, /16)
    float v = 0.f;
    if (tid < R) {
        const int ri = tid / 11;
        const int rj = tid % 11;
        const float* sp = score + bk * L;
        #pragma unroll
        for (int ki = 0; ki < 4; ki++)
            #pragma unroll
            for (int kj = 0; kj < 4; kj++)
                v += sp[(ri + ki) * GH + (rj + kj)];
        v *= (1.f / 16.f);
    }
    sc[tid] = v;
    __syncthreads();

    // min
    red[tid] = (tid < R) ? sc[tid] : FLT_MAX;
    __syncthreads();
    for (int s = 64; s > 0; s >>= 1) {
        if (tid < s) red[tid] = fminf(red[tid], red[tid + s]);
        __syncthreads();
    }
    if (tid == 0) lo_s = red[0];
    __syncthreads();

    // max
    red[tid] = (tid < R) ? sc[tid] : -FLT_MAX;
    __syncthreads();
    for (int s = 64; s > 0; s >>= 1) {
        if (tid < s) red[tid] = fmaxf(red[tid], red[tid + s]);
        __syncthreads();
    }
    if (tid == 0) hi_s = red[0];
    __syncthreads();

    if (tid < R) {
        float inv = 1.f / (hi_s - lo_s + 1e-5f);
        sc[tid] = (sc[tid] - lo_s) * inv;
    }
    __syncthreads();

    // One warp per sample: coalesced noise loads, warp argmax (first-max /
    // lowest-index tie-break, matching lax.top_k semantics)
    const int n = blockIdx.x * 4 + wrp;      // 125*4 = 500 samples
    const float* nn = noise + ((size_t)bk * NS + n) * R;

    float best = -FLT_MAX;
    int   bi   = 0;
    #pragma unroll
    for (int j = 0; j < 4; j++) {
        int r = lane + 32 * j;
        if (r < R) {
            float p = sc[r] + nn[r] * sigma;
            if (p > best) { best = p; bi = r; }
        }
    }
    #pragma unroll
    for (int o = 16; o > 0; o >>= 1) {
        float v2 = __shfl_down_sync(0xffffffffu, best, o);
        int   i2 = __shfl_down_sync(0xffffffffu, bi,   o);
        if (v2 > best || (v2 == best && i2 < bi)) { best = v2; bi = i2; }
    }
    if (lane == 0) g_arg[bk * NS + n] = bi;
}

// ---------------------------------------------------------------------------
// Kernel 2: histogram of 500 argmax indices + ordered compaction. 8 blocks.
// ---------------------------------------------------------------------------
__global__ void compact_kernel()
{
    const int bk  = blockIdx.x;
    const int tid = threadIdx.x;

    __shared__ int cnt[R];
    if (tid < R) cnt[tid] = 0;
    __syncthreads();

    for (int n = tid; n < NS; n += 128)
        atomicAdd(&cnt[g_arg[bk * NS + n]], 1);
    __syncthreads();

    if (tid == 0) {
        int nz = 0;
        for (int r = 0; r < R; r++) {
            int c = cnt[r];
            if (c > 0) {
                int ri = r / 11;
                int rj = r % 11;
                g_wc[bk][nz]  = (float)c * (1.f / (float)NS);
                g_off[bk][nz] = ri * 32 * W + rj * 32;
                nz++;
            }
        }
        g_nnz[bk] = nz;
    }
}

// ---------------------------------------------------------------------------
// Kernel 3: fused gather + weighted sum, float4-vectorized.
// 4 output rows per block; thread (sub,lane) handles row y0+sub, cols lane*4..+3.
// All addresses 16B-aligned (W=448, offsets multiples of 32).
// ---------------------------------------------------------------------------
__global__ void gather_kernel(const float* __restrict__ x,
                              const int*   __restrict__ group_id,
                              float*       __restrict__ out)
{
    const int tid  = threadIdx.x;
    const int sub  = tid >> 5;
    const int lane = tid & 31;

    const int rowbase = blockIdx.x * 4;        // 4 rows share (b,c,t)
    const int rowhi   = rowbase >> 7;          // (b*3+c)*8 + t
    const int y       = (rowbase & (OUTHW - 1)) + sub;
    const int t       = rowhi & 7;
    const int bc      = rowhi >> 3;            // b*3 + c
    const int b       = bc / 3;

    const int bk = b * NKEY + group_id[b * T + t];

    __shared__ float wc[R];
    __shared__ int   off[R];

    const int nnz = g_nnz[bk];
    if (tid < nnz) {
        wc[tid]  = g_wc[bk][tid];
        off[tid] = g_off[bk][tid];
    }
    __syncthreads();

    const size_t xbase = (((size_t)bc * T + t) * H + y) * W + lane * 4;

    float4 acc = make_float4(0.f, 0.f, 0.f, 0.f);
    #pragma unroll 4
    for (int i = 0; i < nnz; i++) {
        const float w = wc[i];
        const float4 v = *reinterpret_cast<const float4*>(x + xbase + off[i]);
        acc.x = fmaf(w, v.x, acc.x);
        acc.y = fmaf(w, v.y, acc.y);
        acc.z = fmaf(w, v.z, acc.z);
        acc.w = fmaf(w, v.w, acc.w);
    }

    *reinterpret_cast<float4*>(out + ((size_t)(rowbase + sub)) * OUTHW + lane * 4) = acc;
}

// ---------------------------------------------------------------------------
// Launch: inputs (metadata order): x, score, noise, sigma, group_id
// ---------------------------------------------------------------------------
extern "C" void kernel_launch(void* const* d_in, const int* in_sizes, int n_in,
                              void* d_out, int out_size)
{
    const float* x        = (const float*)d_in[0];
    const float* score    = (const float*)d_in[1];
    const float* noise    = (const float*)d_in[2];
    const float* sigma    = (const float*)d_in[3];
    const int*   group_id = (const int*)  d_in[4];
    float*       out      = (float*)d_out;

    argmax_kernel<<<dim3(NS / 4, BK), 128>>>(score, noise, sigma);
    compact_kernel<<<BK, 128>>>();

    const int nblocks = (B * C * T * OUTHW) / 4;   // 1536
    gather_kernel<<<nblocks, 128>>>(x, group_id, out);
}

// round 8
// speedup vs baseline: 2.8120x; 1.3383x over previous
#include <cuda_runtime.h>
#include <float.h>

// Problem constants
#define B      2
#define C      3
#define T      8
#define H      448
#define W      448
#define NKEY   4
#define L      196      // 14*14
#define GH     14
#define R      121      // 11*11
#define NS     500
#define BK     (B*NKEY) // 8
#define OUTHW  128      // s*A

// Device scratch (no allocation allowed)
__device__ float g_scn[BK][R];   // normalized region scores
__device__ int   g_cnt[BK][R];   // top-1 histogram

// ---------------------------------------------------------------------------
// Kernel 1: window-mean scores -> min-max norm -> g_scn. Also zeroes g_cnt.
// 8 blocks x 128 threads. Warp-shuffle reductions (2 barriers total).
// ---------------------------------------------------------------------------
__global__ void scorenorm_kernel(const float* __restrict__ score)
{
    const int bk   = blockIdx.x;
    const int tid  = threadIdx.x;
    const int lane = tid & 31;
    const int wrp  = tid >> 5;

    __shared__ float wmin[4], wmax[4];
    __shared__ float lo_s, inv_s;

    // 4x4 window mean over the 14x14 score grid (row-major order, /16)
    float v = 0.f;
    if (tid < R) {
        const int ri = tid / 11;
        const int rj = tid % 11;
        const float* sp = score + bk * L;
        #pragma unroll
        for (int ki = 0; ki < 4; ki++)
            #pragma unroll
            for (int kj = 0; kj < 4; kj++)
                v += sp[(ri + ki) * GH + (rj + kj)];
        v *= (1.f / 16.f);
    }

    float mn = (tid < R) ? v : FLT_MAX;
    float mx = (tid < R) ? v : -FLT_MAX;
    #pragma unroll
    for (int o = 16; o > 0; o >>= 1) {
        mn = fminf(mn, __shfl_down_sync(0xffffffffu, mn, o));
        mx = fmaxf(mx, __shfl_down_sync(0xffffffffu, mx, o));
    }
    if (lane == 0) { wmin[wrp] = mn; wmax[wrp] = mx; }
    __syncthreads();
    if (tid == 0) {
        float lo = fminf(fminf(wmin[0], wmin[1]), fminf(wmin[2], wmin[3]));
        float hi = fmaxf(fmaxf(wmax[0], wmax[1]), fmaxf(wmax[2], wmax[3]));
        lo_s  = lo;
        inv_s = 1.f / (hi - lo + 1e-5f);
    }
    __syncthreads();

    if (tid < R) {
        g_scn[bk][tid] = (v - lo_s) * inv_s;
        g_cnt[bk][tid] = 0;
    }
}

// ---------------------------------------------------------------------------
// Kernel 2: perturbed top-1 argmax, one warp per sample, atomic histogram.
// grid = (ceil(NS/8), BK), block = 256 (8 warps = 8 samples/block).
// Prologue: one smem broadcast of the 121 normalized scores.
// ---------------------------------------------------------------------------
__global__ void argmax_kernel(const float* __restrict__ noise,
                              const float* __restrict__ sigma_p)
{
    const int bk   = blockIdx.y;
    const int tid  = threadIdx.x;
    const int lane = tid & 31;
    const int wrp  = tid >> 5;

    __shared__ float sc[R];
    if (tid < R) sc[tid] = g_scn[bk][tid];
    __syncthreads();

    const int n = blockIdx.x * 8 + wrp;
    if (n >= NS) return;

    const float sigma = sigma_p[0];
    const float* nn = noise + ((size_t)bk * NS + n) * R;

    // Warp argmax with first-max / lowest-index tie-break (lax.top_k semantics)
    float best = -FLT_MAX;
    int   bi   = 0;
    #pragma unroll
    for (int j = 0; j < 4; j++) {
        int r = lane + 32 * j;
        if (r < R) {
            float p = fmaf(nn[r], sigma, sc[r]);
            if (p > best) { best = p; bi = r; }
        }
    }
    #pragma unroll
    for (int o = 16; o > 0; o >>= 1) {
        float v2 = __shfl_down_sync(0xffffffffu, best, o);
        int   i2 = __shfl_down_sync(0xffffffffu, bi,   o);
        if (v2 > best || (v2 == best && i2 < bi)) { best = v2; bi = i2; }
    }
    if (lane == 0) atomicAdd(&g_cnt[bk][bi], 1);
}

// ---------------------------------------------------------------------------
// Kernel 3: fused gather + weighted sum, float4-vectorized, with inline
// order-preserving ballot compaction of the count histogram.
// 4 output rows per block; thread (sub,lane): row y0+sub, cols lane*4..+3.
// ---------------------------------------------------------------------------
__global__ void gather_kernel(const float* __restrict__ x,
                              const int*   __restrict__ group_id,
                              float*       __restrict__ out)
{
    const int tid  = threadIdx.x;
    const int sub  = tid >> 5;
    const int lane = tid & 31;

    const int rowbase = blockIdx.x * 4;        // 4 rows share (b,c,t)
    const int rowhi   = rowbase >> 7;          // (b*3+c)*8 + t
    const int y       = (rowbase & (OUTHW - 1)) + sub;
    const int t       = rowhi & 7;
    const int bc      = rowhi >> 3;            // b*3 + c
    const int b       = bc / 3;

    const int bk = b * NKEY + group_id[b * T + t];

    __shared__ float wc[R];
    __shared__ int   off[R];
    __shared__ int   wbase[4];
    __shared__ int   nnz_s;

    // Ballot compaction: region order preserved => deterministic
    int  cnt = (tid < R) ? g_cnt[bk][tid] : 0;
    bool p   = (cnt > 0);
    unsigned m = __ballot_sync(0xffffffffu, p);
    int within = __popc(m & ((1u << lane) - 1u));
    if (lane == 0) wbase[sub] = __popc(m);
    __syncthreads();
    if (tid == 0) {
        int s = 0;
        #pragma unroll
        for (int w2 = 0; w2 < 4; w2++) { int tt = wbase[w2]; wbase[w2] = s; s += tt; }
        nnz_s = s;
    }
    __syncthreads();
    if (p) {
        int pos = wbase[sub] + within;
        wc[pos]  = (float)cnt * (1.f / (float)NS);
        off[pos] = (tid / 11) * 32 * W + (tid % 11) * 32;
    }
    __syncthreads();

    const int nnz = nnz_s;
    const size_t xbase = (((size_t)bc * T + t) * H + y) * W + lane * 4;

    float4 acc = make_float4(0.f, 0.f, 0.f, 0.f);
    #pragma unroll 4
    for (int i = 0; i < nnz; i++) {
        const float w = wc[i];
        const float4 v = *reinterpret_cast<const float4*>(x + xbase + off[i]);
        acc.x = fmaf(w, v.x, acc.x);
        acc.y = fmaf(w, v.y, acc.y);
        acc.z = fmaf(w, v.z, acc.z);
        acc.w = fmaf(w, v.w, acc.w);
    }

    *reinterpret_cast<float4*>(out + ((size_t)(rowbase + sub)) * OUTHW + lane * 4) = acc;
}

// ---------------------------------------------------------------------------
// Launch: inputs (metadata order): x, score, noise, sigma, group_id
// ---------------------------------------------------------------------------
extern "C" void kernel_launch(void* const* d_in, const int* in_sizes, int n_in,
                              void* d_out, int out_size)
{
    const float* x        = (const float*)d_in[0];
    const float* score    = (const float*)d_in[1];
    const float* noise    = (const float*)d_in[2];
    const float* sigma    = (const float*)d_in[3];
    const int*   group_id = (const int*)  d_in[4];
    float*       out      = (float*)d_out;

    scorenorm_kernel<<<BK, 128>>>(score);
    argmax_kernel<<<dim3((NS + 7) / 8, BK), 256>>>(noise, sigma);

    const int nblocks = (B * C * T * OUTHW) / 4;   // 1536
    gather_kernel<<<nblocks, 128>>>(x, group_id, out);
}